// round 16
// baseline (speedup 1.0000x reference)
#include <cuda_runtime.h>
#include <cstdint>
#include <math.h>

// CTC forward loss via exact forward/backward split at T/2, fused combine.
// B=256, T=1024, C=128, U=128, S=257, blank=127.
// d_in[0]=y_true (int32 B*128), d_in[1]=y_pred (fp32 B*T*C). out: (B) fp32.
//
// Grid 128, block 128 (4 warps): warp w -> batch 2*blockIdx+(w>>1), dir w&1.
// Lane l owns labels/blanks u=4l..4l+3 (lane 31 also blank u=128).
// R14: NO shared-memory staging. Probability gathers are direct LDGs from
// global; L1 coalesces the 5 gathers per row (same 512B row -> first gather
// faults 4 lines, rest hit L1), so L2/DRAM traffic stays exactly one pass.
// Loads pipelined 2 windows ahead into 4 rotating register buffers
// (unroll x4; ~40 outstanding LDGs; no syncs of any kind in the loop).
// Numerics identical to R13: linear domain, per-lane block float, renorm
// every 8 steps, DECAY=48/lane-hop chained prefix-max (2 shfls + Fnb shfl).
// Pairs combine in-block through shared staging after __syncthreads.

#define T_DIM  1024
#define HALF_T 512
#define C_DIM  128
#define BLANK  127
#define EPSV   1e-7f
#define SENT   (-(1 << 28))
#define DECAY  48
#define B_DIM  256

__device__ __forceinline__ float pow2f(int d) {   // exact 2^d; d<=-127 -> 0, clamp +127
    d = min(d, 127);
    return (d <= -127) ? 0.f : __int_as_float((d + 127) << 23);
}

struct WinBuf {
    float qb[4], q0[4], q1[4], q2[4], q3[4];
};

__global__ void __launch_bounds__(128)
ctc_fused_kernel(const int* __restrict__ y_true,
                 const float* __restrict__ y_pred,
                 float* __restrict__ out)
{
    __shared__ float s_vals[4][32][9];
    __shared__ int   s_exps[4][32];

    const int tid = threadIdx.x;
    const int wid = tid >> 5;
    const int l   = tid & 31;
    const int b   = blockIdx.x * 2 + (wid >> 1);
    const int dir = wid & 1;

    const float* __restrict__ P = y_pred + (size_t)b * T_DIM * C_DIM;
    const int*   __restrict__ Y = y_true + (size_t)b * 128;

    const int y0 = Y[4 * l + 0];
    const int y1 = Y[4 * l + 1];
    const int y2 = Y[4 * l + 2];
    const int y3 = Y[4 * l + 3];

    float b0 = 0.f, b1 = 0.f, b2 = 0.f, b3 = 0.f, b4 = 0.f;
    float L0 = 0.f, L1 = 0.f, L2 = 0.f, L3 = 0.f;
    int   E;
    float scale_in = 0.f;
    const float is31 = (l == 31) ? 1.f : 0.f;

    WinBuf BA, BB, BC, BD;

    if (dir == 0) {
        // ================= FORWARD: frames 0..511 -> alpha_511 =================
        const int yprev = (l == 0) ? -1 : Y[4 * l - 1];
        const float al0f = ((l > 0) && (y0 != yprev)) ? 1.f : 0.f;
        const float al1f = (y1 != y0) ? 1.f : 0.f;
        const float al2f = (y2 != y1) ? 1.f : 0.f;
        const float al3f = (y3 != y2) ? 1.f : 0.f;

        // Virtual init: the t=0 step on (b0=1 @ lane0, rest 0) yields alpha_0.
        if (l == 0) b0 = 1.f;
        E = (l == 0) ? 0 : SENT;

        auto loadF = [&](int k, WinBuf& B) {
            // Overreach (k>=128) reads rows 512.. of the same batch: in-bounds,
            // never consumed.
            #pragma unroll
            for (int j = 0; j < 4; ++j) {
                const float* r = P + (size_t)(4 * k + j) * C_DIM;
                B.qb[j] = r[BLANK];
                B.q0[j] = r[y0];
                B.q1[j] = r[y1];
                B.q2[j] = r[y2];
                B.q3[j] = r[y3];
            }
        };
        auto stepF = [&](const WinBuf& B) {
            #pragma unroll
            for (int j = 0; j < 4; ++j) {
                const float qb = B.qb[j] + EPSV;
                const float q0v = B.q0[j] + EPSV;
                const float q1v = B.q1[j] + EPSV;
                const float q2v = B.q2[j] + EPSV;
                const float q3v = B.q3[j] + EPSV;
                const float ap = __shfl_up_sync(0xffffffffu, L3, 1) * scale_in;
                const float nL0 = __fmaf_rn(al0f, ap, L0 + b0) * q0v;
                const float nL1 = __fmaf_rn(al1f, L0, L1 + b1) * q1v;
                const float nL2 = __fmaf_rn(al2f, L1, L2 + b2) * q2v;
                const float nL3 = __fmaf_rn(al3f, L2, L3 + b3) * q3v;
                const float nb0 = (b0 + ap) * qb;
                const float nb1 = (b1 + L0) * qb;
                const float nb2 = (b2 + L1) * qb;
                const float nb3 = (b3 + L2) * qb;
                const float nb4 = __fmaf_rn(is31, L3, b4) * qb;
                L0 = nL0; L1 = nL1; L2 = nL2; L3 = nL3;
                b0 = nb0; b1 = nb1; b2 = nb2; b3 = nb3; b4 = nb4;
            }
        };
        auto renormF = [&]() {
            const float m = fmaxf(fmaxf(fmaxf(L0, L1), fmaxf(L2, L3)),
                                  fmaxf(fmaxf(b0, b1), fmaxf(b2, fmaxf(b3, b4))));
            int Ep = SENT;
            if (m > 0.f) Ep = E + ((__float_as_int(m) >> 23) & 255) - 127;
            const int t1 = __shfl_up_sync(0xffffffffu, Ep, 1);
            int F = (l >= 1) ? max(Ep, t1 - DECAY) : Ep;
            const int t2 = __shfl_up_sync(0xffffffffu, F, 2);
            if (l >= 2) F = max(F, t2 - 2 * DECAY);
            const int Fnb = __shfl_up_sync(0xffffffffu, F, 1);
            const float sc = pow2f(E - F);
            L0 *= sc; L1 *= sc; L2 *= sc; L3 *= sc;
            b0 *= sc; b1 *= sc; b2 *= sc; b3 *= sc; b4 *= sc;
            E = F;
            scale_in = (l == 0) ? 0.f : pow2f(Fnb - F);
        };

        loadF(0, BA);
        loadF(1, BB);
        #pragma unroll 1
        for (int k4 = 0; k4 < 32; ++k4) {
            const int k = 4 * k4;
            loadF(k + 2, BC); stepF(BA);
            loadF(k + 3, BD); stepF(BB); renormF();
            loadF(k + 4, BA); stepF(BC);
            loadF(k + 5, BB); stepF(BD); renormF();
        }
    } else {
        // ================= BACKWARD: frames 1023..512 -> beta_511 =================
        const float al1f = (y1 != y0) ? 1.f : 0.f;
        const float al2f = (y2 != y1) ? 1.f : 0.f;
        const float al3f = (y3 != y2) ? 1.f : 0.f;
        const int   ynx  = (l < 31) ? Y[4 * l + 4] : 0;
        const float alnf = ((l < 31) && (ynx != y3)) ? 1.f : 0.f;

        if (l == 31) { L3 = 1.f; b4 = 1.f; }
        E = (l == 31) ? 0 : SENT;

        auto loadB = [&](int k, WinBuf& B) {
            // Overreach (k>=128) reads rows 495.. of the same batch: in-bounds,
            // never consumed.
            #pragma unroll
            for (int j = 0; j < 4; ++j) {
                const float* r = P + (size_t)(1023 - (4 * k + j)) * C_DIM;
                B.qb[j] = r[BLANK];
                B.q0[j] = r[y0];
                B.q1[j] = r[y1];
                B.q2[j] = r[y2];
                B.q3[j] = r[y3];
            }
        };
        auto stepB = [&](const WinBuf& B) {
            #pragma unroll
            for (int j = 0; j < 4; ++j) {
                const float qb = B.qb[j] + EPSV;
                const float q0v = B.q0[j] + EPSV;
                const float q1v = B.q1[j] + EPSV;
                const float q2v = B.q2[j] + EPSV;
                const float q3v = B.q3[j] + EPSV;
                const float qn = __shfl_down_sync(0xffffffffu, q0v, 1);

                const float sqb = scale_in * qb;
                const float sqn = scale_in * qn;
                const float bn = __shfl_down_sync(0xffffffffu, b0, 1);
                const float Ln = __shfl_down_sync(0xffffffffu, L0, 1);

                const float gb0 = b0 * qb, gb1 = b1 * qb;
                const float gb2 = b2 * qb, gb3 = b3 * qb;
                const float gb4 = b4 * qb;
                const float gL0 = L0 * q0v, gL1 = L1 * q1v;
                const float gL2 = L2 * q2v, gL3 = L3 * q3v;
                const float gbn = bn * sqb;   // lane31: scale_in==0 -> vanishes
                const float gLn = Ln * sqn;

                const float nb0 = gb0 + gL0;
                const float nb1 = gb1 + gL1;
                const float nb2 = gb2 + gL2;
                const float nb3 = gb3 + gL3;
                const float nL0 = __fmaf_rn(al1f, gL1, gL0 + gb1);
                const float nL1 = __fmaf_rn(al2f, gL2, gL1 + gb2);
                const float nL2 = __fmaf_rn(al3f, gL3, gL2 + gb3);
                const float nL3 = __fmaf_rn(alnf, gLn, gL3 + gbn + gb4);

                L0 = nL0; L1 = nL1; L2 = nL2; L3 = nL3;
                b0 = nb0; b1 = nb1; b2 = nb2; b3 = nb3; b4 = gb4;
            }
        };
        auto renormB = [&]() {
            const float m = fmaxf(fmaxf(fmaxf(L0, L1), fmaxf(L2, L3)),
                                  fmaxf(fmaxf(b0, b1), fmaxf(b2, fmaxf(b3, b4))));
            int Ep = SENT;
            if (m > 0.f) Ep = E + ((__float_as_int(m) >> 23) & 255) - 127;
            const int t1 = __shfl_down_sync(0xffffffffu, Ep, 1);
            int F = (l <= 30) ? max(Ep, t1 - DECAY) : Ep;
            const int t2 = __shfl_down_sync(0xffffffffu, F, 2);
            if (l <= 29) F = max(F, t2 - 2 * DECAY);
            const int Fnb = __shfl_down_sync(0xffffffffu, F, 1);
            const float sc = pow2f(E - F);
            L0 *= sc; L1 *= sc; L2 *= sc; L3 *= sc;
            b0 *= sc; b1 *= sc; b2 *= sc; b3 *= sc; b4 *= sc;
            E = F;
            scale_in = (l == 31) ? 0.f : pow2f(Fnb - F);
        };

        loadB(0, BA);
        loadB(1, BB);
        #pragma unroll 1
        for (int k4 = 0; k4 < 32; ++k4) {
            const int k = 4 * k4;
            loadB(k + 2, BC); stepB(BA);
            loadB(k + 3, BD); stepB(BB); renormB();
            loadB(k + 4, BA); stepB(BC);
            loadB(k + 5, BB); stepB(BD); renormB();
        }
    }

    // Publish boundary state to shared staging.
    float* dst = s_vals[wid][l];
    dst[0] = b0; dst[1] = b1; dst[2] = b2; dst[3] = b3;
    dst[4] = L0; dst[5] = L1; dst[6] = L2; dst[7] = L3;
    dst[8] = b4;
    s_exps[wid][l] = E;

    __syncthreads();

    // Warps 0 and 2 combine their (fwd,bwd) pair: ll = sum_s alpha*beta.
    if ((wid & 1) == 0) {
        const float* a = s_vals[wid][l];
        const float* c = s_vals[wid + 1][l];
        float s = 0.f;
        #pragma unroll
        for (int i = 0; i < 9; ++i) s += a[i] * c[i];
        int X = s_exps[wid][l] + s_exps[wid + 1][l];
        if (!(s > 0.f)) { s = 0.f; X = SENT * 2; }

        int M = X;
        #pragma unroll
        for (int off = 16; off; off >>= 1)
            M = max(M, __shfl_xor_sync(0xffffffffu, M, off));

        float v = s * pow2f(X - M);
        #pragma unroll
        for (int off = 16; off; off >>= 1)
            v += __shfl_xor_sync(0xffffffffu, v, off);

        if (l == 0)
            out[b] = (float)(-((double)M * 0.6931471805599453 + log((double)v)));
    }
}

extern "C" void kernel_launch(void* const* d_in, const int* in_sizes, int n_in,
                              void* d_out, int out_size)
{
    const int*   y_true = (const int*)d_in[0];
    const float* y_pred = (const float*)d_in[1];
    float*       out    = (float*)d_out;
    ctc_fused_kernel<<<B_DIM / 2, 128>>>(y_true, y_pred, out);
}

// round 17
// speedup vs baseline: 1.2147x; 1.2147x over previous
#include <cuda_runtime.h>
#include <cstdint>
#include <math.h>

// CTC forward loss: exact fwd/bwd split at T/2, both directions run the SAME
// packed-f32x2 forward-shape recurrence.
// B=256, T=1024, C=128, U=128, S=257, blank=127.
// d_in[0]=y_true (int32 B*128), d_in[1]=y_pred (fp32 B*T*C). out: (B) fp32.
//
// gamma_t[s] := beta_t[s]*q_t[s] obeys the alpha recurrence under state
// reversal s'=256-s with reversed labels, so one step function serves both
// warps. Cut: total = sum_s delta[s]*gamma_512[s], delta = one multiply-free
// alpha half-step, evaluated in the combine with exact exponent alignment.
// Grid 128, block 128 (4 warps): warp w -> batch 2*blockIdx+(w>>1), dir w&1.
// Lane l owns states u=4l..4l+3 (lane31 also u=128). Per-lane block float:
// renorm every 8 steps, DECAY=48/lane-hop chained prefix-max (proven safe:
// <=2 lane crossings/window -> <=2^109). All scaling exact powers of two.
// State packed in f32x2 pairs: FFMA2/FADD2/FMUL2 halve fma-pipe issue.

#define T_DIM  1024
#define HALF_T 512
#define C_DIM  128
#define BLANK  127
#define EPSV   1e-7f
#define RING   16
#define SENT   (-(1 << 28))
#define SENT2  (-(1 << 29))
#define DECAY  48
#define B_DIM  256

__device__ __forceinline__ uint32_t smem_u32(const void* p) {
    uint32_t a;
    asm("{ .reg .u64 t; cvta.to.shared.u64 t, %1; cvt.u32.u64 %0, t; }" : "=r"(a) : "l"(p));
    return a;
}
__device__ __forceinline__ void cp_async16(uint32_t dst, const void* src) {
    asm volatile("cp.async.cg.shared.global [%0], [%1], 16;" :: "r"(dst), "l"(src));
}
__device__ __forceinline__ void cp_commit() {
    asm volatile("cp.async.commit_group;" ::: "memory");
}
__device__ __forceinline__ void cp_wait2() {
    asm volatile("cp.async.wait_group 2;" ::: "memory");
}
__device__ __forceinline__ float pow2f(int d) {   // exact 2^d; d<=-127 -> 0
    d = min(d, 127);
    return (d <= -127) ? 0.f : __int_as_float((d + 127) << 23);
}

// ---- packed f32x2 helpers ----
__device__ __forceinline__ uint64_t pk2(float lo, float hi) {
    uint64_t r; asm("mov.b64 %0, {%1, %2};" : "=l"(r) : "f"(lo), "f"(hi)); return r;
}
__device__ __forceinline__ void upk2(float& lo, float& hi, uint64_t v) {
    asm("mov.b64 {%0, %1}, %2;" : "=f"(lo), "=f"(hi) : "l"(v));
}
__device__ __forceinline__ uint64_t add2(uint64_t a, uint64_t b) {
    uint64_t r; asm("add.rn.f32x2 %0, %1, %2;" : "=l"(r) : "l"(a), "l"(b)); return r;
}
__device__ __forceinline__ uint64_t mul2(uint64_t a, uint64_t b) {
    uint64_t r; asm("mul.rn.f32x2 %0, %1, %2;" : "=l"(r) : "l"(a), "l"(b)); return r;
}
__device__ __forceinline__ uint64_t fma2(uint64_t a, uint64_t b, uint64_t c) {
    uint64_t r; asm("fma.rn.f32x2 %0, %1, %2, %3;" : "=l"(r) : "l"(a), "l"(b), "l"(c)); return r;
}

__global__ void __launch_bounds__(128)
ctc_fused_kernel(const int* __restrict__ y_true,
                 const float* __restrict__ y_pred,
                 float* __restrict__ out)
{
    __shared__ float ring4[4][RING][C_DIM];   // 32 KB
    __shared__ float s_a[4][260];             // flat state values (original coords)
    __shared__ int   s_e[4][260];             // per-state exponents
    __shared__ float s_w[4][260];             // forward allow masks (fwd warps only)

    const int tid = threadIdx.x;
    const int wid = tid >> 5;
    const int l   = tid & 31;
    const int b   = blockIdx.x * 2 + (wid >> 1);
    const int dir = wid & 1;

    const float* __restrict__ P = y_pred + (size_t)b * T_DIM * C_DIM;
    const int*   __restrict__ Y = y_true + (size_t)b * 128;

    // Labels: forward u=4l+j ; backward reversed labels y'_u = Y[127-u].
    const int i0l = dir ? (127 - 4 * l) : (4 * l);
    const int stp = dir ? -1 : 1;
    const int y0 = Y[i0l];
    const int y1 = Y[i0l + stp];
    const int y2 = Y[i0l + 2 * stp];
    const int y3 = Y[i0l + 3 * stp];
    const int yprev = (l > 0) ? Y[i0l - stp] : -1;
    const float al0 = ((l > 0) && (y0 != yprev)) ? 1.f : 0.f;
    const float al1 = (y1 != y0) ? 1.f : 0.f;
    const float al2 = (y2 != y1) ? 1.f : 0.f;
    const float al3 = (y3 != y2) ? 1.f : 0.f;
    const uint64_t AL01 = pk2(al0, al1);
    const uint64_t AL23 = pk2(al2, al3);
    const uint64_t EPS2 = pk2(EPSV, EPSV);

    float (*ring)[C_DIM] = ring4[wid];
    const uint32_t rbase_sh = smem_u32(ring);
    const uint32_t lane_off = l * 16;

    // Packed state: P01=(L0,L1), P23=(L2,L3), Q01=(b0,b1), Q23=(b2,b3), b4.
    // Virtual init: one step on (b0=1 @ lane0) yields alpha_0 / gamma_1023.
    uint64_t P01 = pk2(0.f, 0.f), P23 = pk2(0.f, 0.f);
    uint64_t Q01 = pk2((l == 0) ? 1.f : 0.f, 0.f), Q23 = pk2(0.f, 0.f);
    float b4 = 0.f;
    int   E = (l == 0) ? 0 : SENT;
    float scale_in = 0.f;
    const float is31 = (l == 31) ? 1.f : 0.f;

    struct WB { uint64_t q01[4], q23[4], qbb[4]; float qbs[4]; };
    WB BA, BB;

    auto issue = [&](int kk) {
        const int i0 = 4 * kk;
        if (i0 < HALF_T) {
            #pragma unroll
            for (int j = 0; j < 4; ++j) {
                const int i = i0 + j;
                const int f = dir ? (1023 - i) : i;
                cp_async16(rbase_sh + (uint32_t)(i & (RING - 1)) * (C_DIM * 4) + lane_off,
                           P + (size_t)f * C_DIM + l * 4);
            }
        }
        cp_commit();
    };
    auto gather = [&](int kk, WB& W) {
        #pragma unroll
        for (int j = 0; j < 4; ++j) {
            const float* r = ring[(4 * kk + j) & (RING - 1)];
            const float qb = r[BLANK] + EPSV;
            W.qbs[j] = qb;
            W.qbb[j] = pk2(qb, qb);
            W.q01[j] = add2(pk2(r[y0], r[y1]), EPS2);
            W.q23[j] = add2(pk2(r[y2], r[y3]), EPS2);
        }
    };
    auto step4 = [&](const WB& W) {
        #pragma unroll
        for (int j = 0; j < 4; ++j) {
            float L0, L1, L2, L3;
            upk2(L0, L1, P01); upk2(L2, L3, P23);
            const float ap = __shfl_up_sync(0xffffffffu, L3, 1) * scale_in;  // lane0: 0
            const uint64_t V01 = pk2(ap, L0);
            const uint64_t V23 = pk2(L1, L2);
            const uint64_t S01 = add2(P01, Q01);        // (L0+b0, L1+b1)
            const uint64_t S23 = add2(P23, Q23);
            const uint64_t T01 = fma2(AL01, V01, S01);  // + allow*incoming
            const uint64_t T23 = fma2(AL23, V23, S23);
            const uint64_t U01 = add2(Q01, V01);        // (b0+ap, b1+L0)
            const uint64_t U23 = add2(Q23, V23);
            P01 = mul2(T01, W.q01[j]);
            P23 = mul2(T23, W.q23[j]);
            Q01 = mul2(U01, W.qbb[j]);
            Q23 = mul2(U23, W.qbb[j]);
            b4 = __fmaf_rn(is31, L3, b4) * W.qbs[j];
        }
    };
    auto renorm = [&]() {
        float L0, L1, L2, L3, c0, c1, c2, c3;
        upk2(L0, L1, P01); upk2(L2, L3, P23);
        upk2(c0, c1, Q01); upk2(c2, c3, Q23);
        const float m = fmaxf(fmaxf(fmaxf(L0, L1), fmaxf(L2, L3)),
                              fmaxf(fmaxf(c0, c1), fmaxf(c2, fmaxf(c3, b4))));
        int Ep = SENT;
        if (m > 0.f) Ep = E + ((__float_as_int(m) >> 23) & 255) - 127;
        const int t1 = __shfl_up_sync(0xffffffffu, Ep, 1);
        int F = (l >= 1) ? max(Ep, t1 - DECAY) : Ep;
        const int t2 = __shfl_up_sync(0xffffffffu, F, 2);
        if (l >= 2) F = max(F, t2 - 2 * DECAY);
        const int Fnb = __shfl_up_sync(0xffffffffu, F, 1);
        const float sc = pow2f(E - F);
        const uint64_t SC2 = pk2(sc, sc);
        P01 = mul2(P01, SC2); P23 = mul2(P23, SC2);
        Q01 = mul2(Q01, SC2); Q23 = mul2(Q23, SC2);
        b4 *= sc;
        E = F;
        scale_in = (l == 0) ? 0.f : pow2f(Fnb - F);
    };

    issue(0); issue(1); issue(2);
    cp_wait2(); __syncwarp();
    gather(0, BA);

    #pragma unroll 1
    for (int k2 = 0; k2 < 64; ++k2) {
        {   const int k = 2 * k2;
            issue(k + 3);
            cp_wait2(); __syncwarp();
            gather(k + 1, BB);
            step4(BA);
        }
        {   const int k = 2 * k2 + 1;
            issue(k + 3);
            cp_wait2(); __syncwarp();
            if (k2 < 63) gather(k + 1, BA);
            step4(BB);
            renorm();   // every 8 steps
        }
    }

    // Publish flat state array in ORIGINAL state coordinates.
    {
        float L0, L1, L2, L3, c0, c1, c2, c3;
        upk2(L0, L1, P01); upk2(L2, L3, P23);
        upk2(c0, c1, Q01); upk2(c2, c3, Q23);
        float* Av = s_a[wid]; int* Ae = s_e[wid]; float* Aw = s_w[wid];
        if (dir == 0) {
            const int s = 8 * l;
            Av[s + 0] = c0; Av[s + 1] = L0; Av[s + 2] = c1; Av[s + 3] = L1;
            Av[s + 4] = c2; Av[s + 5] = L2; Av[s + 6] = c3; Av[s + 7] = L3;
            Aw[s + 0] = 0.f; Aw[s + 1] = al0; Aw[s + 2] = 0.f; Aw[s + 3] = al1;
            Aw[s + 4] = 0.f; Aw[s + 5] = al2; Aw[s + 6] = 0.f; Aw[s + 7] = al3;
            #pragma unroll
            for (int i = 0; i < 8; ++i) Ae[s + i] = E;
            if (l == 31) { Av[256] = b4; Aw[256] = 0.f; Ae[256] = E; }
        } else {
            const int s = 256 - 8 * l;   // gamma'[s'] -> original state 256-s'
            Av[s - 0] = c0; Av[s - 1] = L0; Av[s - 2] = c1; Av[s - 3] = L1;
            Av[s - 4] = c2; Av[s - 5] = L2; Av[s - 6] = c3; Av[s - 7] = L3;
            #pragma unroll
            for (int i = 0; i < 8; ++i) Ae[s - i] = E;
            if (l == 31) { Av[0] = b4; Ae[0] = E; }
        }
    }
    __syncthreads();

    // Forward warps combine: total = sum_s delta[s] * gamma_512[s],
    // delta[s] = a[s] + a[s-1] + allowA[s]*a[s-2], all exponent-aligned.
    if (dir == 0) {
        const float* Av = s_a[wid];     const int* Ae = s_e[wid];
        const float* Aw = s_w[wid];
        const float* Gv = s_a[wid + 1]; const int* Ge = s_e[wid + 1];
        int Macc = SENT2;
        float v = 0.f;
        for (int s = l; s < 257; s += 32) {
            const float a0 = Av[s];                  const int e0 = Ae[s];
            const float a1 = (s >= 1) ? Av[s - 1] : 0.f;
            const int   e1 = (s >= 1) ? Ae[s - 1] : SENT2;
            const float a2 = (s >= 2) ? Av[s - 2] * Aw[s] : 0.f;
            const int   e2 = (s >= 2) ? Ae[s - 2] : SENT2;
            const int me = max(e0, max(e1, e2));
            const float delta = a0 * pow2f(e0 - me) + a1 * pow2f(e1 - me)
                              + a2 * pow2f(e2 - me);
            float term = delta * Gv[s];
            int X = me + Ge[s];
            if (!(term > 0.f)) { term = 0.f; X = SENT2; }
            if (X > Macc) { v = v * pow2f(Macc - X) + term; Macc = X; }
            else          { v = __fmaf_rn(term, pow2f(X - Macc), v); }
        }
        int M = Macc;
        #pragma unroll
        for (int off = 16; off; off >>= 1)
            M = max(M, __shfl_xor_sync(0xffffffffu, M, off));
        v = v * pow2f(Macc - M);
        #pragma unroll
        for (int off = 16; off; off >>= 1)
            v += __shfl_xor_sync(0xffffffffu, v, off);
        if (l == 0)
            out[b] = (float)(-((double)M * 0.6931471805599453 + log((double)v)));
    }
}

extern "C" void kernel_launch(void* const* d_in, const int* in_sizes, int n_in,
                              void* d_out, int out_size)
{
    const int*   y_true = (const int*)d_in[0];
    const float* y_pred = (const float*)d_in[1];
    float*       out    = (float*)d_out;
    ctc_fused_kernel<<<B_DIM / 2, 128>>>(y_true, y_pred, out);
}